// round 15
// baseline (speedup 1.0000x reference)
#include <cuda_runtime.h>
#include <cuda_fp16.h>
#include <cstdint>

// Problem constants
#define S_LEN  2048
#define DHEAD  64
#define NHEAD  16
#define NBATCH 2
#define BM     128
#define BN     64
#define TBL    4096
#define TOT    (NBATCH * NHEAD * S_LEN * DHEAD)   // 4,194,304

#define LOG2E      1.4426950408889634f
#define QSCALE     0.18033688011119373f   // 0.125 * log2(e)

// ---------------------------------------------------------------------------
// Global precomputed state: bias (log2-scaled, padded) + fp16 K/V copies
// ---------------------------------------------------------------------------
__device__ float  g_bias[64 + NHEAD * TBL + 256];
__device__ __half g_k16[TOT];
__device__ __half g_v16[TOT];

// pack two f32 -> f16x2, first arg -> low half
__device__ __forceinline__ uint32_t packh(float lo, float hi) {
    uint32_t r;
    asm("cvt.rn.f16x2.f32 %0, %1, %2;" : "=r"(r) : "f"(hi), "f"(lo));
    return r;
}

// Merged preprocess: K/V fp32->fp16 + bias table (log2e-scaled)
__global__ void prep_kernel(const float* __restrict__ k,
                            const float* __restrict__ v,
                            const float* __restrict__ bias_table) {
    int idx = blockIdx.x * blockDim.x + threadIdx.x;
    if (idx < NHEAD * TBL) {
        int h = idx / TBL;
        int n = (idx % TBL) - 2048;  // n = i - j
        int bucket;
        if (n <= 0) {
            bucket = 0;
        } else if (n < 16) {
            bucket = n;
        } else {
            float vf = logf((float)n / 16.0f) / 2.7725887222397811f * 16.0f;
            vf = fminf(vf, 15.0f);
            bucket = 16 + (int)vf;
        }
        g_bias[64 + idx] = bias_table[bucket * NHEAD + h] * LOG2E;
    }
    if (idx < TOT / 4) {
        float4 tk = ((const float4*)k)[idx];
        ((uint2*)g_k16)[idx] = make_uint2(packh(tk.x, tk.y), packh(tk.z, tk.w));
        float4 tv = ((const float4*)v)[idx];
        ((uint2*)g_v16)[idx] = make_uint2(packh(tv.x, tv.y), packh(tv.z, tv.w));
    }
}

// ---------------------------------------------------------------------------
// PTX helpers (portable, plain sm_103 target)
// ---------------------------------------------------------------------------
__device__ __forceinline__ uint32_t smem_u32(const void* p) {
    uint32_t a;
    asm("{ .reg .u64 t; cvta.to.shared.u64 t, %1; cvt.u32.u64 %0, t; }" : "=r"(a) : "l"(p));
    return a;
}
__device__ __forceinline__ float ex2(float x) {
    float y;
    asm("ex2.approx.ftz.f32 %0, %1;" : "=f"(y) : "f"(x));
    return y;
}
// fused: pack (x,y) to f16x2 then 2^() both halves in one MUFU op
__device__ __forceinline__ uint32_t h2ex2(float x, float y) {
    uint32_t t = packh(x, y);
    uint32_t r;
    asm("ex2.approx.f16x2 %0, %1;" : "=r"(r) : "r"(t));
    return r;
}
__device__ __forceinline__ uint32_t hadd2u(uint32_t a, uint32_t b) {
    uint32_t r;
    asm("add.rn.f16x2 %0, %1, %2;" : "=r"(r) : "r"(a), "r"(b));
    return r;
}
__device__ __forceinline__ float2 h22f2(uint32_t p) {
    __half2 h = *(__half2*)&p;
    return __half22float2(h);
}

#define MMAH(d, a, b0v, b1v) \
    asm volatile("mma.sync.aligned.m16n8k16.row.col.f32.f16.f16.f32 " \
        "{%0,%1,%2,%3}, {%4,%5,%6,%7}, {%8,%9}, {%0,%1,%2,%3};" \
        : "+f"((d)[0]), "+f"((d)[1]), "+f"((d)[2]), "+f"((d)[3]) \
        : "r"((a)[0]), "r"((a)[1]), "r"((a)[2]), "r"((a)[3]), "r"(b0v), "r"(b1v))

#define LDSM4(r, addr) \
    asm volatile("ldmatrix.sync.aligned.m8n8.x4.shared.b16 {%0,%1,%2,%3}, [%4];" \
        : "=r"((r)[0]), "=r"((r)[1]), "=r"((r)[2]), "=r"((r)[3]) : "r"(addr))

#define LDSM4T(r, addr) \
    asm volatile("ldmatrix.sync.aligned.m8n8.x4.trans.shared.b16 {%0,%1,%2,%3}, [%4];" \
        : "=r"((r)[0]), "=r"((r)[1]), "=r"((r)[2]), "=r"((r)[3]) : "r"(addr))

#define CP16(dst, src) \
    asm volatile("cp.async.cg.shared.global [%0], [%1], 16;" :: "r"(dst), "l"(src))
#define CP_COMMIT() asm volatile("cp.async.commit_group;" ::: "memory")
#define CP_WAIT0()  asm volatile("cp.async.wait_group 0;" ::: "memory")
#define CP_WAIT1()  asm volatile("cp.async.wait_group 1;" ::: "memory")

// ---------------------------------------------------------------------------
// SMEM layout (bytes). fp16 tiles: row stride 72 halves (144B, ldmatrix-safe)
// K double-buffered, V triple-buffered (pipeline hazard), bias double.
// ---------------------------------------------------------------------------
#define KSTR 72
#define OFF_Q   0        // 128*72*2 = 18432 (Q staging; frags hoisted)
#define OFF_K0  18432    // 9216 each
#define OFF_K1  27648
#define OFF_V0  36864    // 9216 each x3
#define OFF_V1  46080
#define OFF_V2  55296
#define OFF_B0  64512    // 1024 each
#define OFF_B1  65536
#define SMEM_TOTAL 66560

// ---------------------------------------------------------------------------
// One CTA = 128 query rows of one (b,h); 4 warps, warp w owns rows 32w..32w+31.
// Software-pipelined: iteration j runs PV[j] and S[j+1] as independent MMA
// streams, then softmax[j+1] (consumed next iteration).
// ---------------------------------------------------------------------------
__global__ void __launch_bounds__(128, 2)
attn_mma_kernel(const float* __restrict__ q,
                const int* __restrict__ event_length_i32,
                float* __restrict__ out) {
    extern __shared__ char smem[];
    const uint32_t sb = smem_u32(smem);

    const int tid = threadIdx.x;
    const int w   = tid >> 5;
    const int l   = tid & 31;
    const int qr  = l >> 2;          // 0..7
    const int qc2 = (l & 3) * 2;     // 0,2,4,6
    const int g   = l >> 3;          // ldmatrix lane group
    const int gr  = l & 7;

    const int b  = blockIdx.z;
    const int h  = blockIdx.y;
    const int i0 = blockIdx.x * BM;

    const long long base = ((long long)(b * NHEAD + h)) * S_LEN * DHEAD;
    const float*  qh  = q + base;
    const __half* k16 = g_k16 + base;
    const __half* v16 = g_v16 + base;
    float*        oh  = out + base;

    const int L = (event_length_i32[1] == 0) ? event_length_i32[2 * b]
                                             : event_length_i32[b];
    const int jend = min(S_LEN, ((L + BN - 1) / BN) * BN);

    const float* biasrow = g_bias + 64 + h * TBL + 2048;

    // --- copy issue helper (K+V+bias for one 64-key tile) ---
    auto issue_tile = [&](int jb, uint32_t kOff, uint32_t vOff, uint32_t bOff) {
        const __half* kn = k16 + jb * DHEAD;
        const __half* vn = v16 + jb * DHEAD;
        #pragma unroll
        for (int it = 0; it < 4; it++) {
            int c = tid + it * 128;
            int row = c >> 3, c16 = (c & 7) * 8;
            uint32_t soff = (uint32_t)(row * KSTR + c16) * 2;
            CP16(sb + kOff + soff, kn + row * DHEAD + c16);
            CP16(sb + vOff + soff, vn + row * DHEAD + c16);
        }
        if (tid < 64) CP16(sb + bOff + tid * 16, biasrow + (i0 - jb) - 64 + tid * 4);
    };

    // --- prologue copies: tile0 (group0), tile1 (group1) ---
    issue_tile(0, OFF_K0, OFF_V0, OFF_B0);
    CP_COMMIT();
    issue_tile(BN, OFF_K1, OFF_V1, OFF_B1);   // rows always in-bounds (S=2048)
    CP_COMMIT();

    // --- stage Q (LDG, overlaps copies) ---
    #pragma unroll
    for (int it = 0; it < 16; it++) {
        int idx = tid + it * 128;        // 128 rows * 16 float4
        int row = idx >> 4;
        int c4  = (idx & 15) << 2;
        float4 t = *(const float4*)(qh + (i0 + row) * DHEAD + c4);
        uint32_t u0 = packh(t.x * QSCALE, t.y * QSCALE);
        uint32_t u1 = packh(t.z * QSCALE, t.w * QSCALE);
        *(uint2*)(smem + OFF_Q + (uint32_t)(row * KSTR + c4) * 2) = make_uint2(u0, u1);
    }
    CP_WAIT1();          // tile0 resident (tile1 may still be in flight)
    __syncthreads();

    // --- hoist Q fragments (two row-frags per warp, tile-invariant) ---
    const int arow = 32 * w + ((g & 1) << 3) + gr;
    uint32_t qf[2][4][4];
    #pragma unroll
    for (int r = 0; r < 2; r++) {
        #pragma unroll
        for (int kk = 0; kk < 4; kk++) {
            int ad = 16 * kk + ((g >> 1) << 3);
            LDSM4(qf[r][kk],
                  sb + OFF_Q + (uint32_t)((arow + 16 * r) * KSTR + ad) * 2);
        }
    }

    float oacc[2][32];
    #pragma unroll
    for (int r = 0; r < 2; r++)
        #pragma unroll
        for (int i = 0; i < 32; i++) oacc[r][i] = 0.0f;
    float mO[4], lp[4];
    #pragma unroll
    for (int i = 0; i < 4; i++) { mO[i] = -1e30f; lp[i] = 0.0f; }

    const int ri0 = 32 * w + qr;
    float sacc[2][32];
    uint32_t pf[2][4][4];

    // --- S-only compute (prologue) ---
    auto computeS = [&](uint32_t offK) {
        #pragma unroll
        for (int r = 0; r < 2; r++)
            #pragma unroll
            for (int i = 0; i < 32; i++) sacc[r][i] = 0.0f;
        #pragma unroll
        for (int kk = 0; kk < 4; kk++) {
            #pragma unroll
            for (int t2 = 0; t2 < 4; t2++) {
                int key = 16 * t2 + ((g >> 1) << 3) + gr;
                int d0  = 16 * kk + ((g & 1) << 3);
                uint32_t off = (uint32_t)(key * KSTR + d0) * 2;
                uint32_t kb[4];
                LDSM4(kb, sb + offK + off);
                #pragma unroll
                for (int r = 0; r < 2; r++) {
                    MMAH((sacc[r] + 8 * t2),     qf[r][kk], kb[0], kb[1]);
                    MMAH((sacc[r] + 8 * t2 + 4), qf[r][kk], kb[2], kb[3]);
                }
            }
        }
    };

    // --- softmax for tile base jb (bias buffer sB) -> pf ---
    auto softmaxT = [&](int jb, const float* sB) {
        #pragma unroll
        for (int r = 0; r < 2; r++) {
            int rA = ri0 + 16 * r;
            #pragma unroll
            for (int n = 0; n < 8; n++) {
                int cj = 8 * n + qc2;
                sacc[r][4 * n + 0] += sB[rA - cj + 64];
                sacc[r][4 * n + 1] += sB[rA - cj + 63];
                sacc[r][4 * n + 2] += sB[rA - cj + 72];
                sacc[r][4 * n + 3] += sB[rA - cj + 71];
            }
        }
        if (jb + BN > L) {
            #pragma unroll
            for (int r = 0; r < 2; r++) {
                #pragma unroll
                for (int n = 0; n < 8; n++) {
                    int cj = 8 * n + qc2;
                    if (jb + cj >= L)     { sacc[r][4 * n + 0] = -1e9f; sacc[r][4 * n + 2] = -1e9f; }
                    if (jb + cj + 1 >= L) { sacc[r][4 * n + 1] = -1e9f; sacc[r][4 * n + 3] = -1e9f; }
                }
            }
        }
        float lm[4];
        #pragma unroll
        for (int r = 0; r < 2; r++) {
            float a0 = -1e30f, a1 = -1e30f;
            #pragma unroll
            for (int n = 0; n < 8; n++) {
                a0 = fmaxf(a0, fmaxf(sacc[r][4 * n + 0], sacc[r][4 * n + 1]));
                a1 = fmaxf(a1, fmaxf(sacc[r][4 * n + 2], sacc[r][4 * n + 3]));
            }
            lm[2 * r] = a0; lm[2 * r + 1] = a1;
        }
        bool need = (lm[0] > mO[0] + 10.0f) || (lm[1] > mO[1] + 10.0f) ||
                    (lm[2] > mO[2] + 10.0f) || (lm[3] > mO[3] + 10.0f);
        if (__any_sync(0xffffffffu, need)) {
            #pragma unroll
            for (int g4 = 0; g4 < 4; g4++) {
                float mx = lm[g4];
                mx = fmaxf(mx, __shfl_xor_sync(0xffffffffu, mx, 1));
                mx = fmaxf(mx, __shfl_xor_sync(0xffffffffu, mx, 2));
                float mn = fmaxf(mO[g4], mx);
                float sc = ex2(mO[g4] - mn);
                lp[g4] *= sc;
                mO[g4] = mn;
                float* oa = oacc[g4 >> 1] + ((g4 & 1) ? 2 : 0);
                #pragma unroll
                for (int i = 0; i < 8; i++) {
                    oa[4 * i + 0] *= sc;
                    oa[4 * i + 1] *= sc;
                }
            }
        }
        #pragma unroll
        for (int r = 0; r < 2; r++) {
            float f0 = mO[2 * r], f1 = mO[2 * r + 1];
            #pragma unroll
            for (int kk2 = 0; kk2 < 4; kk2++) {
                float* pa = sacc[r] + 8 * kk2;
                pf[r][kk2][0] = h2ex2(pa[0] - f0, pa[1] - f0);
                pf[r][kk2][1] = h2ex2(pa[2] - f1, pa[3] - f1);
                pf[r][kk2][2] = h2ex2(pa[4] - f0, pa[5] - f0);
                pf[r][kk2][3] = h2ex2(pa[6] - f1, pa[7] - f1);
            }
            uint32_t u0a = hadd2u(pf[r][0][0], pf[r][1][0]);
            uint32_t u0b = hadd2u(pf[r][2][0], pf[r][3][0]);
            uint32_t u0c = hadd2u(pf[r][0][2], pf[r][1][2]);
            uint32_t u0d = hadd2u(pf[r][2][2], pf[r][3][2]);
            float2 fa = h22f2(hadd2u(u0a, u0b));
            float2 fb = h22f2(hadd2u(u0c, u0d));
            lp[2 * r] += (fa.x + fa.y) + (fb.x + fb.y);
            uint32_t u1a = hadd2u(pf[r][0][1], pf[r][1][1]);
            uint32_t u1b = hadd2u(pf[r][2][1], pf[r][3][1]);
            uint32_t u1c = hadd2u(pf[r][0][3], pf[r][1][3]);
            uint32_t u1d = hadd2u(pf[r][2][3], pf[r][3][3]);
            float2 fc = h22f2(hadd2u(u1a, u1b));
            float2 fd = h22f2(hadd2u(u1c, u1d));
            lp[2 * r + 1] += (fc.x + fc.y) + (fd.x + fd.y);
        }
    };

    // --- prologue compute: S[0] + softmax[0] -> pf ---
    computeS(OFF_K0);
    softmaxT(0, (const float*)(smem + OFF_B0));

    int bufit = 0;   // parity of current tile j
    int vi    = 0;   // V buffer of current tile j
    for (int j0 = 0; ; j0 += BN) {
        const uint32_t offVcur = OFF_V0 + (uint32_t)vi * 9216;
        const bool last = (j0 + BN >= jend);

        if (last) {
            // --- final PV only ---
            #pragma unroll
            for (int kk2 = 0; kk2 < 4; kk2++) {
                int key = 16 * kk2 + ((g & 1) << 3) + gr;
                #pragma unroll
                for (int t2 = 0; t2 < 4; t2++) {
                    int d0 = 16 * t2 + ((g >> 1) << 3);
                    uint32_t off = (uint32_t)(key * KSTR + d0) * 2;
                    uint32_t vb[4];
                    LDSM4T(vb, sb + offVcur + off);
                    #pragma unroll
                    for (int r = 0; r < 2; r++) {
                        MMAH((oacc[r] + 8 * t2),     pf[r][kk2], vb[0], vb[1]);
                        MMAH((oacc[r] + 8 * t2 + 4), pf[r][kk2], vb[2], vb[3]);
                    }
                }
            }
            break;
        }

        // tile j+1 data resident; buffers K[bufit]/B[bufit] free for reuse
        CP_WAIT0();
        __syncthreads();
        if (j0 + 2 * BN < jend) {
            issue_tile(j0 + 2 * BN,
                       bufit ? OFF_K1 : OFF_K0,
                       OFF_V0 + (uint32_t)(((vi + 2) % 3)) * 9216,
                       bufit ? OFF_B1 : OFF_B0);
        }
        CP_COMMIT();

        // --- interleaved: PV[j] (oacc) + S[j+1] (sacc) — independent streams ---
        const uint32_t offKn = bufit ? OFF_K0 : OFF_K1;   // K buffer of tile j+1
        #pragma unroll
        for (int r = 0; r < 2; r++)
            #pragma unroll
            for (int i = 0; i < 32; i++) sacc[r][i] = 0.0f;

        #pragma unroll
        for (int kk = 0; kk < 4; kk++) {
            // S chunk: d-chunk kk over all key chunks
            #pragma unroll
            for (int t2 = 0; t2 < 4; t2++) {
                int key = 16 * t2 + ((g >> 1) << 3) + gr;
                int d0  = 16 * kk + ((g & 1) << 3);
                uint32_t off = (uint32_t)(key * KSTR + d0) * 2;
                uint32_t kb[4];
                LDSM4(kb, sb + offKn + off);
                #pragma unroll
                for (int r = 0; r < 2; r++) {
                    MMAH((sacc[r] + 8 * t2),     qf[r][kk], kb[0], kb[1]);
                    MMAH((sacc[r] + 8 * t2 + 4), qf[r][kk], kb[2], kb[3]);
                }
            }
            // PV chunk: key-chunk kk over all d chunks
            int key2 = 16 * kk + ((g & 1) << 3) + gr;
            #pragma unroll
            for (int t2 = 0; t2 < 4; t2++) {
                int d0 = 16 * t2 + ((g >> 1) << 3);
                uint32_t off = (uint32_t)(key2 * KSTR + d0) * 2;
                uint32_t vb[4];
                LDSM4T(vb, sb + offVcur + off);
                #pragma unroll
                for (int r = 0; r < 2; r++) {
                    MMAH((oacc[r] + 8 * t2),     pf[r][kk], vb[0], vb[1]);
                    MMAH((oacc[r] + 8 * t2 + 4), pf[r][kk], vb[2], vb[3]);
                }
            }
        }

        // --- softmax[j+1] -> pf (consumed next iteration) ---
        softmaxT(j0 + BN, (const float*)(smem + (bufit ? OFF_B0 : OFF_B1)));

        bufit ^= 1;
        vi = (vi + 1) % 3;
    }
    CP_WAIT0();   // drain any unconsumed prefetch before exit

    // --- epilogue: reduce l across quad, normalize, store ---
    float inv[4];
    #pragma unroll
    for (int g4 = 0; g4 < 4; g4++) {
        float s = lp[g4];
        s += __shfl_xor_sync(0xffffffffu, s, 1);
        s += __shfl_xor_sync(0xffffffffu, s, 2);
        inv[g4] = 1.0f / s;
    }
    #pragma unroll
    for (int r = 0; r < 2; r++) {
        int grow0 = i0 + ri0 + 16 * r;
        int grow1 = grow0 + 8;
        #pragma unroll
        for (int n = 0; n < 8; n++) {
            *(float2*)(oh + grow0 * DHEAD + 8 * n + qc2) =
                make_float2(oacc[r][4 * n + 0] * inv[2 * r],
                            oacc[r][4 * n + 1] * inv[2 * r]);
            *(float2*)(oh + grow1 * DHEAD + 8 * n + qc2) =
                make_float2(oacc[r][4 * n + 2] * inv[2 * r + 1],
                            oacc[r][4 * n + 3] * inv[2 * r + 1]);
        }
    }
}

// ---------------------------------------------------------------------------
extern "C" void kernel_launch(void* const* d_in, const int* in_sizes, int n_in,
                              void* d_out, int out_size) {
    const float* q          = (const float*)d_in[0];
    const float* k          = (const float*)d_in[1];
    const float* v          = (const float*)d_in[2];
    const float* bias_table = (const float*)d_in[3];
    const int*   event_len  = (const int*)d_in[4];
    float*       out        = (float*)d_out;

    (void)in_sizes; (void)n_in; (void)out_size;

    prep_kernel<<<(TOT / 4 + 255) / 256, 256>>>(k, v, bias_table);

    cudaFuncSetAttribute(attn_mma_kernel, cudaFuncAttributeMaxDynamicSharedMemorySize,
                         SMEM_TOTAL);

    dim3 grid(S_LEN / BM, NHEAD, NBATCH);
    attn_mma_kernel<<<grid, 128, SMEM_TOTAL>>>(q, event_len, out);
}

// round 16
// speedup vs baseline: 1.0091x; 1.0091x over previous
#include <cuda_runtime.h>
#include <cuda_fp16.h>
#include <cstdint>

// Problem constants
#define S_LEN  2048
#define DHEAD  64
#define NHEAD  16
#define NBATCH 2
#define BM     128
#define BN     64
#define TBL    4096
#define TOT    (NBATCH * NHEAD * S_LEN * DHEAD)   // 4,194,304
#define NITEMS (NBATCH * NHEAD * (S_LEN / BM))    // 512

#define LOG2E      1.4426950408889634f
#define QSCALE     0.18033688011119373f   // 0.125 * log2(e)

// ---------------------------------------------------------------------------
// Global precomputed state + work counter
// ---------------------------------------------------------------------------
__device__ float        g_bias[64 + NHEAD * TBL + 256];
__device__ __half       g_k16[TOT];
__device__ __half       g_v16[TOT];
__device__ unsigned int g_ctr;

// pack two f32 -> f16x2, first arg -> low half
__device__ __forceinline__ uint32_t packh(float lo, float hi) {
    uint32_t r;
    asm("cvt.rn.f16x2.f32 %0, %1, %2;" : "=r"(r) : "f"(hi), "f"(lo));
    return r;
}

// Merged preprocess: K/V fp32->fp16 + bias table (log2e-scaled) + counter reset
__global__ void prep_kernel(const float* __restrict__ k,
                            const float* __restrict__ v,
                            const float* __restrict__ bias_table) {
    int idx = blockIdx.x * blockDim.x + threadIdx.x;
    if (idx == 0) g_ctr = 0;
    if (idx < NHEAD * TBL) {
        int h = idx / TBL;
        int n = (idx % TBL) - 2048;  // n = i - j
        int bucket;
        if (n <= 0) {
            bucket = 0;
        } else if (n < 16) {
            bucket = n;
        } else {
            float vf = logf((float)n / 16.0f) / 2.7725887222397811f * 16.0f;
            vf = fminf(vf, 15.0f);
            bucket = 16 + (int)vf;
        }
        g_bias[64 + idx] = bias_table[bucket * NHEAD + h] * LOG2E;
    }
    if (idx < TOT / 4) {
        float4 tk = ((const float4*)k)[idx];
        ((uint2*)g_k16)[idx] = make_uint2(packh(tk.x, tk.y), packh(tk.z, tk.w));
        float4 tv = ((const float4*)v)[idx];
        ((uint2*)g_v16)[idx] = make_uint2(packh(tv.x, tv.y), packh(tv.z, tv.w));
    }
}

// ---------------------------------------------------------------------------
// PTX helpers (portable, plain sm_103 target)
// ---------------------------------------------------------------------------
__device__ __forceinline__ uint32_t smem_u32(const void* p) {
    uint32_t a;
    asm("{ .reg .u64 t; cvta.to.shared.u64 t, %1; cvt.u32.u64 %0, t; }" : "=r"(a) : "l"(p));
    return a;
}
__device__ __forceinline__ float ex2(float x) {
    float y;
    asm("ex2.approx.ftz.f32 %0, %1;" : "=f"(y) : "f"(x));
    return y;
}
// fused: pack (x,y) to f16x2 then 2^() both halves in one MUFU op
__device__ __forceinline__ uint32_t h2ex2(float x, float y) {
    uint32_t t = packh(x, y);
    uint32_t r;
    asm("ex2.approx.f16x2 %0, %1;" : "=r"(r) : "r"(t));
    return r;
}
__device__ __forceinline__ uint32_t hadd2u(uint32_t a, uint32_t b) {
    uint32_t r;
    asm("add.rn.f16x2 %0, %1, %2;" : "=r"(r) : "r"(a), "r"(b));
    return r;
}
__device__ __forceinline__ float2 h22f2(uint32_t p) {
    __half2 h = *(__half2*)&p;
    return __half22float2(h);
}

#define MMAH(d, a, b0v, b1v) \
    asm volatile("mma.sync.aligned.m16n8k16.row.col.f32.f16.f16.f32 " \
        "{%0,%1,%2,%3}, {%4,%5,%6,%7}, {%8,%9}, {%0,%1,%2,%3};" \
        : "+f"((d)[0]), "+f"((d)[1]), "+f"((d)[2]), "+f"((d)[3]) \
        : "r"((a)[0]), "r"((a)[1]), "r"((a)[2]), "r"((a)[3]), "r"(b0v), "r"(b1v))

#define LDSM4(r, addr) \
    asm volatile("ldmatrix.sync.aligned.m8n8.x4.shared.b16 {%0,%1,%2,%3}, [%4];" \
        : "=r"((r)[0]), "=r"((r)[1]), "=r"((r)[2]), "=r"((r)[3]) : "r"(addr))

#define LDSM4T(r, addr) \
    asm volatile("ldmatrix.sync.aligned.m8n8.x4.trans.shared.b16 {%0,%1,%2,%3}, [%4];" \
        : "=r"((r)[0]), "=r"((r)[1]), "=r"((r)[2]), "=r"((r)[3]) : "r"(addr))

#define CP16(dst, src) \
    asm volatile("cp.async.cg.shared.global [%0], [%1], 16;" :: "r"(dst), "l"(src))
#define CP_COMMIT() asm volatile("cp.async.commit_group;" ::: "memory")
#define CP_WAIT0()  asm volatile("cp.async.wait_group 0;" ::: "memory")

// ---------------------------------------------------------------------------
// SMEM layout (bytes). fp16 tiles: row stride 72 halves (144B, ldmatrix-safe)
// ---------------------------------------------------------------------------
#define KSTR 72
#define OFF_Q    0        // 128*72*2 = 18432 (Q staging; frags hoisted)
#define OFF_K0   18432    // 64*72*2 = 9216 each
#define OFF_V0   27648
#define OFF_K1   36864
#define OFF_V1   46080
#define OFF_B0   55296    // 256 floats each
#define OFF_B1   56320
#define OFF_ITEM 57344    // 16 bytes
#define SMEM_TOTAL 57360

// ---------------------------------------------------------------------------
// Persistent CTAs (2/SM), dynamic work stealing over 512 (i,h,b) items,
// longest batch first. Per-item body identical to the best R14 kernel.
// ---------------------------------------------------------------------------
__global__ void __launch_bounds__(128, 2)
attn_mma_kernel(const float* __restrict__ q,
                const int* __restrict__ event_length_i32,
                float* __restrict__ out) {
    extern __shared__ char smem[];
    const uint32_t sb = smem_u32(smem);

    const int tid = threadIdx.x;
    const int w   = tid >> 5;
    const int l   = tid & 31;
    const int qr  = l >> 2;          // 0..7
    const int qc2 = (l & 3) * 2;     // 0,2,4,6
    const int g   = l >> 3;          // ldmatrix lane group
    const int gr  = l & 7;

    // decode both batch lengths once (int64 vs int32 layout)
    const bool is64 = (event_length_i32[1] == 0);
    const int  Lv0  = is64 ? event_length_i32[0] : event_length_i32[0];
    const int  Lv1  = is64 ? event_length_i32[2] : event_length_i32[1];
    const int  blong = (Lv0 >= Lv1) ? 0 : 1;   // longer batch scheduled first

    volatile int* sItem = (volatile int*)(smem + OFF_ITEM);

    for (;;) {
        // --- grab next work item ---
        if (tid == 0) *sItem = (int)atomicAdd(&g_ctr, 1u);
        __syncthreads();
        const int item = *sItem;
        __syncthreads();
        if (item >= NITEMS) break;

        const int braw = item >> 8;          // 0..1 (0 dispatched first)
        const int h    = (item >> 4) & 15;
        const int i0   = (item & 15) * BM;
        const int b    = braw ? (1 - blong) : blong;
        const int L    = b ? Lv1 : Lv0;
        const int jend = min(S_LEN, ((L + BN - 1) / BN) * BN);

        const long long base = ((long long)(b * NHEAD + h)) * S_LEN * DHEAD;
        const float*  qh  = q + base;
        const __half* k16 = g_k16 + base;
        const __half* v16 = g_v16 + base;
        float*        oh  = out + base;
        const float* biasrow = g_bias + 64 + h * TBL + 2048;

        // --- prologue: async-copy tile0 K/V + bias0; LDG-convert Q ---
        #pragma unroll
        for (int it = 0; it < 4; it++) {
            int c = tid + it * 128;
            int row = c >> 3, c16 = (c & 7) * 8;
            uint32_t soff = (uint32_t)(row * KSTR + c16) * 2;
            CP16(sb + OFF_K0 + soff, k16 + row * DHEAD + c16);
            CP16(sb + OFF_V0 + soff, v16 + row * DHEAD + c16);
        }
        if (tid < 64) CP16(sb + OFF_B0 + tid * 16, biasrow + i0 - 64 + tid * 4);
        CP_COMMIT();

        #pragma unroll
        for (int it = 0; it < 16; it++) {
            int idx = tid + it * 128;
            int row = idx >> 4;
            int c4  = (idx & 15) << 2;
            float4 t = *(const float4*)(qh + (i0 + row) * DHEAD + c4);
            uint32_t u0 = packh(t.x * QSCALE, t.y * QSCALE);
            uint32_t u1 = packh(t.z * QSCALE, t.w * QSCALE);
            *(uint2*)(smem + OFF_Q + (uint32_t)(row * KSTR + c4) * 2) = make_uint2(u0, u1);
        }
        CP_WAIT0();
        __syncthreads();

        // --- hoist Q fragments ---
        const int arow = 32 * w + ((g & 1) << 3) + gr;
        uint32_t qf[2][4][4];
        #pragma unroll
        for (int r = 0; r < 2; r++) {
            #pragma unroll
            for (int kk = 0; kk < 4; kk++) {
                int ad = 16 * kk + ((g >> 1) << 3);
                LDSM4(qf[r][kk],
                      sb + OFF_Q + (uint32_t)((arow + 16 * r) * KSTR + ad) * 2);
            }
        }

        float oacc[2][32];
        #pragma unroll
        for (int r = 0; r < 2; r++)
            #pragma unroll
            for (int i = 0; i < 32; i++) oacc[r][i] = 0.0f;
        float mO[4], lp[4];
        #pragma unroll
        for (int i = 0; i < 4; i++) { mO[i] = -1e30f; lp[i] = 0.0f; }

        const int ri0 = 32 * w + qr;

        int bufit = 0;
        for (int j0 = 0; j0 < jend; j0 += BN, bufit ^= 1) {
            const uint32_t offK = OFF_K0 + (uint32_t)bufit * 18432;
            const uint32_t offV = OFF_V0 + (uint32_t)bufit * 18432;
            const float*   sB   = (const float*)(smem + OFF_B0 + bufit * 1024);

            // --- prefetch next tile (overlaps compute) ---
            if (j0 + BN < jend) {
                const __half* kn = k16 + (j0 + BN) * DHEAD;
                const __half* vn = v16 + (j0 + BN) * DHEAD;
                uint32_t nK = OFF_K0 + (uint32_t)(bufit ^ 1) * 18432;
                uint32_t nV = OFF_V0 + (uint32_t)(bufit ^ 1) * 18432;
                #pragma unroll
                for (int it = 0; it < 4; it++) {
                    int c = tid + it * 128;
                    int row = c >> 3, c16 = (c & 7) * 8;
                    uint32_t soff = (uint32_t)(row * KSTR + c16) * 2;
                    CP16(sb + nK + soff, kn + row * DHEAD + c16);
                    CP16(sb + nV + soff, vn + row * DHEAD + c16);
                }
                if (tid < 64)
                    CP16(sb + OFF_B0 + (bufit ^ 1) * 1024 + tid * 16,
                         biasrow + (i0 - j0 - BN) - 64 + tid * 4);
            }
            CP_COMMIT();

            // --- S = q~ K~^T ---
            float sacc[2][32];
            #pragma unroll
            for (int r = 0; r < 2; r++)
                #pragma unroll
                for (int i = 0; i < 32; i++) sacc[r][i] = 0.0f;

            #pragma unroll
            for (int kk = 0; kk < 4; kk++) {
                #pragma unroll
                for (int t2 = 0; t2 < 4; t2++) {
                    int key = 16 * t2 + ((g >> 1) << 3) + gr;
                    int d0  = 16 * kk + ((g & 1) << 3);
                    uint32_t off = (uint32_t)(key * KSTR + d0) * 2;
                    uint32_t kb[4];
                    LDSM4(kb, sb + offK + off);
                    #pragma unroll
                    for (int r = 0; r < 2; r++) {
                        MMAH((sacc[r] + 8 * t2),     qf[r][kk], kb[0], kb[1]);
                        MMAH((sacc[r] + 8 * t2 + 4), qf[r][kk], kb[2], kb[3]);
                    }
                }
            }

            // --- bias add ---
            #pragma unroll
            for (int r = 0; r < 2; r++) {
                int rA = ri0 + 16 * r;
                #pragma unroll
                for (int n = 0; n < 8; n++) {
                    int cj = 8 * n + qc2;
                    sacc[r][4 * n + 0] += sB[rA - cj + 64];
                    sacc[r][4 * n + 1] += sB[rA - cj + 63];
                    sacc[r][4 * n + 2] += sB[rA - cj + 72];
                    sacc[r][4 * n + 3] += sB[rA - cj + 71];
                }
            }
            // --- key mask only on the straddling tile ---
            if (j0 + BN > L) {
                #pragma unroll
                for (int r = 0; r < 2; r++) {
                    #pragma unroll
                    for (int n = 0; n < 8; n++) {
                        int cj = 8 * n + qc2;
                        if (j0 + cj >= L)     { sacc[r][4 * n + 0] = -1e9f; sacc[r][4 * n + 2] = -1e9f; }
                        if (j0 + cj + 1 >= L) { sacc[r][4 * n + 1] = -1e9f; sacc[r][4 * n + 3] = -1e9f; }
                    }
                }
            }

            // --- lazy frame check ---
            float lm[4];
            #pragma unroll
            for (int r = 0; r < 2; r++) {
                float a0 = -1e30f, a1 = -1e30f;
                #pragma unroll
                for (int n = 0; n < 8; n++) {
                    a0 = fmaxf(a0, fmaxf(sacc[r][4 * n + 0], sacc[r][4 * n + 1]));
                    a1 = fmaxf(a1, fmaxf(sacc[r][4 * n + 2], sacc[r][4 * n + 3]));
                }
                lm[2 * r] = a0; lm[2 * r + 1] = a1;
            }
            bool need = (lm[0] > mO[0] + 10.0f) || (lm[1] > mO[1] + 10.0f) ||
                        (lm[2] > mO[2] + 10.0f) || (lm[3] > mO[3] + 10.0f);
            if (__any_sync(0xffffffffu, need)) {
                #pragma unroll
                for (int g4 = 0; g4 < 4; g4++) {
                    float mx = lm[g4];
                    mx = fmaxf(mx, __shfl_xor_sync(0xffffffffu, mx, 1));
                    mx = fmaxf(mx, __shfl_xor_sync(0xffffffffu, mx, 2));
                    float mn = fmaxf(mO[g4], mx);
                    float sc = ex2(mO[g4] - mn);
                    lp[g4] *= sc;
                    mO[g4] = mn;
                    float* oa = oacc[g4 >> 1] + ((g4 & 1) ? 2 : 0);
                    #pragma unroll
                    for (int i = 0; i < 8; i++) {
                        oa[4 * i + 0] *= sc;
                        oa[4 * i + 1] *= sc;
                    }
                }
            }

            // --- P = ex2.f16x2(s - m) directly into fragments + fp16 row sums ---
            uint32_t pf[2][4][4];
            #pragma unroll
            for (int r = 0; r < 2; r++) {
                float f0 = mO[2 * r], f1 = mO[2 * r + 1];
                #pragma unroll
                for (int kk2 = 0; kk2 < 4; kk2++) {
                    float* pa = sacc[r] + 8 * kk2;
                    pf[r][kk2][0] = h2ex2(pa[0] - f0, pa[1] - f0);
                    pf[r][kk2][1] = h2ex2(pa[2] - f1, pa[3] - f1);
                    pf[r][kk2][2] = h2ex2(pa[4] - f0, pa[5] - f0);
                    pf[r][kk2][3] = h2ex2(pa[6] - f1, pa[7] - f1);
                }
                uint32_t u0a = hadd2u(pf[r][0][0], pf[r][1][0]);
                uint32_t u0b = hadd2u(pf[r][2][0], pf[r][3][0]);
                uint32_t u0c = hadd2u(pf[r][0][2], pf[r][1][2]);
                uint32_t u0d = hadd2u(pf[r][2][2], pf[r][3][2]);
                float2 fa = h22f2(hadd2u(u0a, u0b));
                float2 fb = h22f2(hadd2u(u0c, u0d));
                lp[2 * r] += (fa.x + fa.y) + (fb.x + fb.y);
                uint32_t u1a = hadd2u(pf[r][0][1], pf[r][1][1]);
                uint32_t u1b = hadd2u(pf[r][2][1], pf[r][3][1]);
                uint32_t u1c = hadd2u(pf[r][0][3], pf[r][1][3]);
                uint32_t u1d = hadd2u(pf[r][2][3], pf[r][3][3]);
                float2 fc = h22f2(hadd2u(u1a, u1b));
                float2 fd = h22f2(hadd2u(u1c, u1d));
                lp[2 * r + 1] += (fc.x + fc.y) + (fd.x + fd.y);
            }

            // --- O += P V~ ---
            #pragma unroll
            for (int kk2 = 0; kk2 < 4; kk2++) {
                int key = 16 * kk2 + ((g & 1) << 3) + gr;
                #pragma unroll
                for (int t2 = 0; t2 < 4; t2++) {
                    int d0 = 16 * t2 + ((g >> 1) << 3);
                    uint32_t off = (uint32_t)(key * KSTR + d0) * 2;
                    uint32_t vb[4];
                    LDSM4T(vb, sb + offV + off);
                    #pragma unroll
                    for (int r = 0; r < 2; r++) {
                        MMAH((oacc[r] + 8 * t2),     pf[r][kk2], vb[0], vb[1]);
                        MMAH((oacc[r] + 8 * t2 + 4), pf[r][kk2], vb[2], vb[3]);
                    }
                }
            }

            CP_WAIT0();
            __syncthreads();
        }

        // --- epilogue: reduce l across quad, normalize, store ---
        float inv[4];
        #pragma unroll
        for (int g4 = 0; g4 < 4; g4++) {
            float s = lp[g4];
            s += __shfl_xor_sync(0xffffffffu, s, 1);
            s += __shfl_xor_sync(0xffffffffu, s, 2);
            inv[g4] = 1.0f / s;
        }
        #pragma unroll
        for (int r = 0; r < 2; r++) {
            int grow0 = i0 + ri0 + 16 * r;
            int grow1 = grow0 + 8;
            #pragma unroll
            for (int n = 0; n < 8; n++) {
                *(float2*)(oh + grow0 * DHEAD + 8 * n + qc2) =
                    make_float2(oacc[r][4 * n + 0] * inv[2 * r],
                                oacc[r][4 * n + 1] * inv[2 * r]);
                *(float2*)(oh + grow1 * DHEAD + 8 * n + qc2) =
                    make_float2(oacc[r][4 * n + 2] * inv[2 * r + 1],
                                oacc[r][4 * n + 3] * inv[2 * r + 1]);
            }
        }
        // loop back for next item (top-of-loop barrier orders smem reuse)
    }
}

// ---------------------------------------------------------------------------
extern "C" void kernel_launch(void* const* d_in, const int* in_sizes, int n_in,
                              void* d_out, int out_size) {
    const float* q          = (const float*)d_in[0];
    const float* k          = (const float*)d_in[1];
    const float* v          = (const float*)d_in[2];
    const float* bias_table = (const float*)d_in[3];
    const int*   event_len  = (const int*)d_in[4];
    float*       out        = (float*)d_out;

    (void)in_sizes; (void)n_in; (void)out_size;

    prep_kernel<<<(TOT / 4 + 255) / 256, 256>>>(k, v, bias_table);

    cudaFuncSetAttribute(attn_mma_kernel, cudaFuncAttributeMaxDynamicSharedMemorySize,
                         SMEM_TOTAL);

    attn_mma_kernel<<<296, 128, SMEM_TOTAL>>>(q, event_len, out);
}

// round 17
// speedup vs baseline: 1.0885x; 1.0787x over previous
#include <cuda_runtime.h>
#include <cuda_fp16.h>
#include <cstdint>

// Problem constants
#define S_LEN  2048
#define DHEAD  64
#define NHEAD  16
#define NBATCH 2
#define BM     128
#define BN     64
#define TBL    4096
#define TOT    (NBATCH * NHEAD * S_LEN * DHEAD)   // 4,194,304

#define LOG2E      1.4426950408889634f
#define QSCALE     0.18033688011119373f   // 0.125 * log2(e)

// ---------------------------------------------------------------------------
// Global precomputed state: bias (log2-scaled, padded) + fp16 K/V copies
// ---------------------------------------------------------------------------
__device__ float  g_bias[64 + NHEAD * TBL + 256];
__device__ __half g_k16[TOT];
__device__ __half g_v16[TOT];

// pack two f32 -> f16x2, first arg -> low half
__device__ __forceinline__ uint32_t packh(float lo, float hi) {
    uint32_t r;
    asm("cvt.rn.f16x2.f32 %0, %1, %2;" : "=r"(r) : "f"(hi), "f"(lo));
    return r;
}

// Merged preprocess: K/V fp32->fp16 + bias table (log2e-scaled)
__global__ void prep_kernel(const float* __restrict__ k,
                            const float* __restrict__ v,
                            const float* __restrict__ bias_table) {
    int idx = blockIdx.x * blockDim.x + threadIdx.x;
    if (idx < NHEAD * TBL) {
        int h = idx / TBL;
        int n = (idx % TBL) - 2048;  // n = i - j
        int bucket;
        if (n <= 0) {
            bucket = 0;
        } else if (n < 16) {
            bucket = n;
        } else {
            float vf = logf((float)n / 16.0f) / 2.7725887222397811f * 16.0f;
            vf = fminf(vf, 15.0f);
            bucket = 16 + (int)vf;
        }
        g_bias[64 + idx] = bias_table[bucket * NHEAD + h] * LOG2E;
    }
    if (idx < TOT / 4) {
        float4 tk = ((const float4*)k)[idx];
        ((uint2*)g_k16)[idx] = make_uint2(packh(tk.x, tk.y), packh(tk.z, tk.w));
        float4 tv = ((const float4*)v)[idx];
        ((uint2*)g_v16)[idx] = make_uint2(packh(tv.x, tv.y), packh(tv.z, tv.w));
    }
}

// ---------------------------------------------------------------------------
// PTX helpers (portable, plain sm_103 target)
// ---------------------------------------------------------------------------
__device__ __forceinline__ uint32_t smem_u32(const void* p) {
    uint32_t a;
    asm("{ .reg .u64 t; cvta.to.shared.u64 t, %1; cvt.u32.u64 %0, t; }" : "=r"(a) : "l"(p));
    return a;
}
__device__ __forceinline__ float ex2(float x) {
    float y;
    asm("ex2.approx.ftz.f32 %0, %1;" : "=f"(y) : "f"(x));
    return y;
}
// fused: pack (x,y) to f16x2 then 2^() both halves in one MUFU op
__device__ __forceinline__ uint32_t h2ex2(float x, float y) {
    uint32_t t = packh(x, y);
    uint32_t r;
    asm("ex2.approx.f16x2 %0, %1;" : "=r"(r) : "r"(t));
    return r;
}
__device__ __forceinline__ uint32_t hadd2u(uint32_t a, uint32_t b) {
    uint32_t r;
    asm("add.rn.f16x2 %0, %1, %2;" : "=r"(r) : "r"(a), "r"(b));
    return r;
}
__device__ __forceinline__ float2 h22f2(uint32_t p) {
    __half2 h = *(__half2*)&p;
    return __half22float2(h);
}

#define MMAH(d, a, b0v, b1v) \
    asm volatile("mma.sync.aligned.m16n8k16.row.col.f32.f16.f16.f32 " \
        "{%0,%1,%2,%3}, {%4,%5,%6,%7}, {%8,%9}, {%0,%1,%2,%3};" \
        : "+f"((d)[0]), "+f"((d)[1]), "+f"((d)[2]), "+f"((d)[3]) \
        : "r"((a)[0]), "r"((a)[1]), "r"((a)[2]), "r"((a)[3]), "r"(b0v), "r"(b1v))

#define LDSM4(r, addr) \
    asm volatile("ldmatrix.sync.aligned.m8n8.x4.shared.b16 {%0,%1,%2,%3}, [%4];" \
        : "=r"((r)[0]), "=r"((r)[1]), "=r"((r)[2]), "=r"((r)[3]) : "r"(addr))

#define LDSM4T(r, addr) \
    asm volatile("ldmatrix.sync.aligned.m8n8.x4.trans.shared.b16 {%0,%1,%2,%3}, [%4];" \
        : "=r"((r)[0]), "=r"((r)[1]), "=r"((r)[2]), "=r"((r)[3]) : "r"(addr))

#define CP16(dst, src) \
    asm volatile("cp.async.cg.shared.global [%0], [%1], 16;" :: "r"(dst), "l"(src))
#define CP_COMMIT() asm volatile("cp.async.commit_group;" ::: "memory")
#define CP_WAIT0()  asm volatile("cp.async.wait_group 0;" ::: "memory")

// ---------------------------------------------------------------------------
// SMEM layout (bytes). fp16 tiles: row stride 72 halves (144B, ldmatrix-safe)
// ---------------------------------------------------------------------------
#define KSTR 72
#define OFF_Q   0        // 128*72*2 = 18432 (Q staging; frags hoisted)
#define OFF_K0  18432    // 64*72*2 = 9216 each
#define OFF_V0  27648
#define OFF_K1  36864
#define OFF_V1  46080
#define OFF_B0  55296    // 256 floats each
#define OFF_B1  56320
#define SMEM_TOTAL 57344

// ---------------------------------------------------------------------------
// One CTA = 128 query rows of one (b,h); 4 warps, warp w owns rows 32w..32w+31.
// R14 schedule + front-loaded LDSM groups (4 loads in flight per MMA burst).
// ---------------------------------------------------------------------------
__global__ void __launch_bounds__(128, 2)
attn_mma_kernel(const float* __restrict__ q,
                const int* __restrict__ event_length_i32,
                float* __restrict__ out) {
    extern __shared__ char smem[];
    const uint32_t sb = smem_u32(smem);

    const int tid = threadIdx.x;
    const int w   = tid >> 5;
    const int l   = tid & 31;
    const int qr  = l >> 2;          // 0..7
    const int qc2 = (l & 3) * 2;     // 0,2,4,6
    const int g   = l >> 3;          // ldmatrix lane group
    const int gr  = l & 7;

    const int b  = blockIdx.z;
    const int h  = blockIdx.y;
    const int i0 = blockIdx.x * BM;

    const long long base = ((long long)(b * NHEAD + h)) * S_LEN * DHEAD;
    const float*  qh  = q + base;
    const __half* k16 = g_k16 + base;
    const __half* v16 = g_v16 + base;
    float*        oh  = out + base;

    const int L = (event_length_i32[1] == 0) ? event_length_i32[2 * b]
                                             : event_length_i32[b];
    const int jend = min(S_LEN, ((L + BN - 1) / BN) * BN);

    const float* biasrow = g_bias + 64 + h * TBL + 2048;

    // --- prologue: async-copy tile0 K/V + bias0; LDG-convert Q (overlaps) ---
    #pragma unroll
    for (int it = 0; it < 4; it++) {
        int c = tid + it * 128;          // 64 rows * 8 chunks
        int row = c >> 3, c16 = (c & 7) * 8;
        uint32_t soff = (uint32_t)(row * KSTR + c16) * 2;
        CP16(sb + OFF_K0 + soff, k16 + row * DHEAD + c16);
        CP16(sb + OFF_V0 + soff, v16 + row * DHEAD + c16);
    }
    if (tid < 64) CP16(sb + OFF_B0 + tid * 16, biasrow + i0 - 64 + tid * 4);
    CP_COMMIT();

    #pragma unroll
    for (int it = 0; it < 16; it++) {
        int idx = tid + it * 128;        // 128 rows * 16 float4
        int row = idx >> 4;
        int c4  = (idx & 15) << 2;
        float4 t = *(const float4*)(qh + (i0 + row) * DHEAD + c4);
        uint32_t u0 = packh(t.x * QSCALE, t.y * QSCALE);
        uint32_t u1 = packh(t.z * QSCALE, t.w * QSCALE);
        *(uint2*)(smem + OFF_Q + (uint32_t)(row * KSTR + c4) * 2) = make_uint2(u0, u1);
    }
    CP_WAIT0();
    __syncthreads();

    // --- hoist Q fragments (two row-frags per warp, tile-invariant) ---
    const int arow = 32 * w + ((g & 1) << 3) + gr;
    uint32_t qf[2][4][4];
    #pragma unroll
    for (int r = 0; r < 2; r++) {
        #pragma unroll
        for (int kk = 0; kk < 4; kk++) {
            int ad = 16 * kk + ((g >> 1) << 3);
            LDSM4(qf[r][kk],
                  sb + OFF_Q + (uint32_t)((arow + 16 * r) * KSTR + ad) * 2);
        }
    }

    float oacc[2][32];
    #pragma unroll
    for (int r = 0; r < 2; r++)
        #pragma unroll
        for (int i = 0; i < 32; i++) oacc[r][i] = 0.0f;
    float mO[4], lp[4];
    #pragma unroll
    for (int i = 0; i < 4; i++) { mO[i] = -1e30f; lp[i] = 0.0f; }

    const int ri0 = 32 * w + qr;     // tile-local row (frag r adds 16r, +8 for d2/d3)

    int bufit = 0;
    for (int j0 = 0; j0 < jend; j0 += BN, bufit ^= 1) {
        const uint32_t offK = OFF_K0 + (uint32_t)bufit * 18432;
        const uint32_t offV = OFF_V0 + (uint32_t)bufit * 18432;
        const float*   sB   = (const float*)(smem + OFF_B0 + bufit * 1024);

        // --- prefetch next tile into the other buffers (overlaps compute) ---
        if (j0 + BN < jend) {
            const __half* kn = k16 + (j0 + BN) * DHEAD;
            const __half* vn = v16 + (j0 + BN) * DHEAD;
            uint32_t nK = OFF_K0 + (uint32_t)(bufit ^ 1) * 18432;
            uint32_t nV = OFF_V0 + (uint32_t)(bufit ^ 1) * 18432;
            #pragma unroll
            for (int it = 0; it < 4; it++) {
                int c = tid + it * 128;
                int row = c >> 3, c16 = (c & 7) * 8;
                uint32_t soff = (uint32_t)(row * KSTR + c16) * 2;
                CP16(sb + nK + soff, kn + row * DHEAD + c16);
                CP16(sb + nV + soff, vn + row * DHEAD + c16);
            }
            if (tid < 64)
                CP16(sb + OFF_B0 + (bufit ^ 1) * 1024 + tid * 16,
                     biasrow + (i0 - j0 - BN) - 64 + tid * 4);
        }
        CP_COMMIT();

        // --- S = q~ K~^T : front-loaded LDSM group, then 16-MMA burst per kk ---
        float sacc[2][32];
        #pragma unroll
        for (int r = 0; r < 2; r++)
            #pragma unroll
            for (int i = 0; i < 32; i++) sacc[r][i] = 0.0f;

        #pragma unroll
        for (int kk = 0; kk < 4; kk++) {
            int d0 = 16 * kk + ((g & 1) << 3);
            uint32_t kb[4][4];
            #pragma unroll
            for (int t2 = 0; t2 < 4; t2++) {
                int key = 16 * t2 + ((g >> 1) << 3) + gr;
                LDSM4(kb[t2], sb + offK + (uint32_t)(key * KSTR + d0) * 2);
            }
            #pragma unroll
            for (int t2 = 0; t2 < 4; t2++) {
                #pragma unroll
                for (int r = 0; r < 2; r++) {
                    MMAH((sacc[r] + 8 * t2),     qf[r][kk], kb[t2][0], kb[t2][1]);
                    MMAH((sacc[r] + 8 * t2 + 4), qf[r][kk], kb[t2][2], kb[t2][3]);
                }
            }
        }

        // --- bias add (always) ---
        #pragma unroll
        for (int r = 0; r < 2; r++) {
            int rA = ri0 + 16 * r;
            #pragma unroll
            for (int n = 0; n < 8; n++) {
                int cj = 8 * n + qc2;
                sacc[r][4 * n + 0] += sB[rA - cj + 64];
                sacc[r][4 * n + 1] += sB[rA - cj + 63];
                sacc[r][4 * n + 2] += sB[rA - cj + 72];
                sacc[r][4 * n + 3] += sB[rA - cj + 71];
            }
        }
        // --- key mask only on the tile straddling L (uniform branch) ---
        if (j0 + BN > L) {
            #pragma unroll
            for (int r = 0; r < 2; r++) {
                #pragma unroll
                for (int n = 0; n < 8; n++) {
                    int cj = 8 * n + qc2;
                    if (j0 + cj >= L)     { sacc[r][4 * n + 0] = -1e9f; sacc[r][4 * n + 2] = -1e9f; }
                    if (j0 + cj + 1 >= L) { sacc[r][4 * n + 1] = -1e9f; sacc[r][4 * n + 3] = -1e9f; }
                }
            }
        }

        // --- lazy frame check: local maxes + one warp vote ---
        float lm[4];
        #pragma unroll
        for (int r = 0; r < 2; r++) {
            float a0 = -1e30f, a1 = -1e30f;
            #pragma unroll
            for (int n = 0; n < 8; n++) {
                a0 = fmaxf(a0, fmaxf(sacc[r][4 * n + 0], sacc[r][4 * n + 1]));
                a1 = fmaxf(a1, fmaxf(sacc[r][4 * n + 2], sacc[r][4 * n + 3]));
            }
            lm[2 * r] = a0; lm[2 * r + 1] = a1;
        }
        bool need = (lm[0] > mO[0] + 10.0f) || (lm[1] > mO[1] + 10.0f) ||
                    (lm[2] > mO[2] + 10.0f) || (lm[3] > mO[3] + 10.0f);
        if (__any_sync(0xffffffffu, need)) {
            #pragma unroll
            for (int g4 = 0; g4 < 4; g4++) {
                float mx = lm[g4];
                mx = fmaxf(mx, __shfl_xor_sync(0xffffffffu, mx, 1));
                mx = fmaxf(mx, __shfl_xor_sync(0xffffffffu, mx, 2));
                float mn = fmaxf(mO[g4], mx);
                float sc = ex2(mO[g4] - mn);
                lp[g4] *= sc;
                mO[g4] = mn;
                float* oa = oacc[g4 >> 1] + ((g4 & 1) ? 2 : 0);
                #pragma unroll
                for (int i = 0; i < 8; i++) {
                    oa[4 * i + 0] *= sc;
                    oa[4 * i + 1] *= sc;
                }
            }
        }

        // --- P = ex2.f16x2(s - m) directly into fragments + fp16 row sums ---
        uint32_t pf[2][4][4];
        #pragma unroll
        for (int r = 0; r < 2; r++) {
            float f0 = mO[2 * r], f1 = mO[2 * r + 1];
            #pragma unroll
            for (int kk2 = 0; kk2 < 4; kk2++) {
                float* pa = sacc[r] + 8 * kk2;
                pf[r][kk2][0] = h2ex2(pa[0] - f0, pa[1] - f0);
                pf[r][kk2][1] = h2ex2(pa[2] - f1, pa[3] - f1);
                pf[r][kk2][2] = h2ex2(pa[4] - f0, pa[5] - f0);
                pf[r][kk2][3] = h2ex2(pa[6] - f1, pa[7] - f1);
            }
            uint32_t u0a = hadd2u(pf[r][0][0], pf[r][1][0]);
            uint32_t u0b = hadd2u(pf[r][2][0], pf[r][3][0]);
            uint32_t u0c = hadd2u(pf[r][0][2], pf[r][1][2]);
            uint32_t u0d = hadd2u(pf[r][2][2], pf[r][3][2]);
            float2 fa = h22f2(hadd2u(u0a, u0b));
            float2 fb = h22f2(hadd2u(u0c, u0d));
            lp[2 * r] += (fa.x + fa.y) + (fb.x + fb.y);
            uint32_t u1a = hadd2u(pf[r][0][1], pf[r][1][1]);
            uint32_t u1b = hadd2u(pf[r][2][1], pf[r][3][1]);
            uint32_t u1c = hadd2u(pf[r][0][3], pf[r][1][3]);
            uint32_t u1d = hadd2u(pf[r][2][3], pf[r][3][3]);
            float2 fc = h22f2(hadd2u(u1a, u1b));
            float2 fd = h22f2(hadd2u(u1c, u1d));
            lp[2 * r + 1] += (fc.x + fc.y) + (fd.x + fd.y);
        }

        // --- O += P V~ : front-loaded LDSM4T group, then 16-MMA burst per kk2 ---
        #pragma unroll
        for (int kk2 = 0; kk2 < 4; kk2++) {
            int key = 16 * kk2 + ((g & 1) << 3) + gr;
            uint32_t vb[4][4];
            #pragma unroll
            for (int t2 = 0; t2 < 4; t2++) {
                int d0 = 16 * t2 + ((g >> 1) << 3);
                LDSM4T(vb[t2], sb + offV + (uint32_t)(key * KSTR + d0) * 2);
            }
            #pragma unroll
            for (int t2 = 0; t2 < 4; t2++) {
                #pragma unroll
                for (int r = 0; r < 2; r++) {
                    MMAH((oacc[r] + 8 * t2),     pf[r][kk2], vb[t2][0], vb[t2][1]);
                    MMAH((oacc[r] + 8 * t2 + 4), pf[r][kk2], vb[t2][2], vb[t2][3]);
                }
            }
        }

        // --- make next tile resident & visible (single barrier per tile) ---
        CP_WAIT0();
        __syncthreads();
    }

    // --- epilogue: reduce l across quad, normalize, store ---
    float inv[4];
    #pragma unroll
    for (int g4 = 0; g4 < 4; g4++) {
        float s = lp[g4];
        s += __shfl_xor_sync(0xffffffffu, s, 1);
        s += __shfl_xor_sync(0xffffffffu, s, 2);
        inv[g4] = 1.0f / s;
    }
    #pragma unroll
    for (int r = 0; r < 2; r++) {
        int grow0 = i0 + ri0 + 16 * r;
        int grow1 = grow0 + 8;
        #pragma unroll
        for (int n = 0; n < 8; n++) {
            *(float2*)(oh + grow0 * DHEAD + 8 * n + qc2) =
                make_float2(oacc[r][4 * n + 0] * inv[2 * r],
                            oacc[r][4 * n + 1] * inv[2 * r]);
            *(float2*)(oh + grow1 * DHEAD + 8 * n + qc2) =
                make_float2(oacc[r][4 * n + 2] * inv[2 * r + 1],
                            oacc[r][4 * n + 3] * inv[2 * r + 1]);
        }
    }
}

// ---------------------------------------------------------------------------
extern "C" void kernel_launch(void* const* d_in, const int* in_sizes, int n_in,
                              void* d_out, int out_size) {
    const float* q          = (const float*)d_in[0];
    const float* k          = (const float*)d_in[1];
    const float* v          = (const float*)d_in[2];
    const float* bias_table = (const float*)d_in[3];
    const int*   event_len  = (const int*)d_in[4];
    float*       out        = (float*)d_out;

    (void)in_sizes; (void)n_in; (void)out_size;

    prep_kernel<<<(TOT / 4 + 255) / 256, 256>>>(k, v, bias_table);

    cudaFuncSetAttribute(attn_mma_kernel, cudaFuncAttributeMaxDynamicSharedMemorySize,
                         SMEM_TOTAL);

    dim3 grid(S_LEN / BM, NHEAD, NBATCH);
    attn_mma_kernel<<<grid, 128, SMEM_TOTAL>>>(q, event_len, out);
}